// round 16
// baseline (speedup 1.0000x reference)
#include <cuda_runtime.h>
#include <cuda_fp16.h>
#include <math.h>
#include <stdint.h>

// Problem constants
#define B_ 2
#define L_ 2048
#define D_ 2048
#define H_ 8
#define HD_ 256
#define FD_ 64
#define FEAT_ 128          // 2*FD
#define CHUNK_ 64
#define NCH_ (L_/CHUNK_)   // 32
#define HALF_ (HD_/2)      // 128

// ---------------- scratch (device globals; no allocation allowed) ----------
__device__ float g_q [B_*L_*H_*HD_];
__device__ float g_k [B_*L_*HD_];
__device__ float g_v [B_*L_*HD_];
__device__ float g_kv[B_*H_*NCH_*FEAT_*HD_];          // per-chunk states (fp32)
__device__ __half g_kvh[B_*H_*NCH_*FEAT_*HD_];        // exclusive prefix (fp16)
__device__ __half g_qfh[B_*H_*L_*FEAT_];              // hedgehog q (fp16)
__device__ __half g_kfh[B_*H_*L_*FEAT_];              // hedgehog k (fp16)
__device__ __half g_vh [B_*L_*HD_];                   // v (fp16)

__device__ __half g_hh[B_*L_*D_];
__device__ __half g_oh[B_*L_*H_*HD_];
__device__ __half g_wqh[D_*H_*HD_];
__device__ __half g_wkh[HD_*D_];
__device__ __half g_wvh[HD_*D_];
__device__ __half g_woh[D_*H_*HD_];

// ---------------- helpers ---------------------------------------------------
__device__ __forceinline__ void mma_f16(float* d,
                                        const uint32_t* a,
                                        const uint32_t* b) {
    asm volatile(
        "mma.sync.aligned.m16n8k16.row.col.f32.f16.f16.f32 "
        "{%0,%1,%2,%3}, {%4,%5,%6,%7}, {%8,%9}, {%0,%1,%2,%3};\n"
        : "+f"(d[0]), "+f"(d[1]), "+f"(d[2]), "+f"(d[3])
        : "r"(a[0]), "r"(a[1]), "r"(a[2]), "r"(a[3]),
          "r"(b[0]), "r"(b[1]));
}
__device__ __forceinline__ void cp16s(uint32_t saddr, const void* g) {
    asm volatile("cp.async.cg.shared.global [%0], [%1], 16;\n"
                 :: "r"(saddr), "l"(g));
}
__device__ __forceinline__ void cp_commit() {
    asm volatile("cp.async.commit_group;\n");
}
__device__ __forceinline__ void ldsm4(uint32_t* r, uint32_t saddr) {
    asm volatile("ldmatrix.sync.aligned.m8n8.x4.shared.b16 {%0,%1,%2,%3}, [%4];\n"
                 : "=r"(r[0]), "=r"(r[1]), "=r"(r[2]), "=r"(r[3]) : "r"(saddr));
}
__device__ __forceinline__ void ldsm4t(uint32_t* r, uint32_t saddr) {
    asm volatile("ldmatrix.sync.aligned.m8n8.x4.trans.shared.b16 {%0,%1,%2,%3}, [%4];\n"
                 : "=r"(r[0]), "=r"(r[1]), "=r"(r[2]), "=r"(r[3]) : "r"(saddr));
}

// ---------------- convert kernels ------------------------------------------
__global__ __launch_bounds__(256)
void cvt_kernel(const float* __restrict__ x, __half* __restrict__ hi,
                int off, int n) {
    int i = off + (blockIdx.x*256 + threadIdx.x)*8;
    if (i >= off + n) return;
    float4 a = *(const float4*)(x + i);
    float4 b = *(const float4*)(x + i + 4);
    __half2* o = (__half2*)(hi + i);
    o[0] = __floats2half2_rn(a.x, a.y);
    o[1] = __floats2half2_rn(a.z, a.w);
    o[2] = __floats2half2_rn(b.x, b.y);
    o[3] = __floats2half2_rn(b.z, b.w);
}

// All four weight transposes in one launch. z: 0=Wq, 1=Wo, 2=Wk, 3=Wv.
__global__ __launch_bounds__(256)
void splitT_all_kernel(const float* __restrict__ Wq, __half* tq,
                       const float* __restrict__ Wo, __half* to,
                       const float* __restrict__ Wk, __half* tk,
                       const float* __restrict__ Wv, __half* tv) {
    int z = blockIdx.z;
    const float* W; __half* th; int K, N;
    if      (z == 0) { W = Wq; th = tq; K = D_;     N = H_*HD_; }
    else if (z == 1) { W = Wo; th = to; K = H_*HD_; N = D_;     }
    else if (z == 2) { W = Wk; th = tk; K = D_;     N = HD_;    }
    else             { W = Wv; th = tv; K = D_;     N = HD_;    }
    int n0 = blockIdx.x*32, k0 = blockIdx.y*32;
    if (n0 >= N || k0 >= K) return;
    __shared__ float tile[32][33];
    int tx = threadIdx.x & 31, ty = threadIdx.x >> 5;
    #pragma unroll
    for (int r = 0; r < 32; r += 8)
        tile[ty + r][tx] = W[(size_t)(k0 + ty + r)*N + n0 + tx];
    __syncthreads();
    #pragma unroll
    for (int r = 0; r < 32; r += 8) {
        float v = tile[tx][ty + r];
        th[(size_t)(n0 + ty + r)*K + k0 + tx] = __float2half_rn(v);
    }
}

// ============================================================================
// hgemm: single-term fp16 GEMM — R11 measured config. DO NOT TOUCH.
// ============================================================================
#define LDWW 12
#define SECW (128*LDWW)
#define STW  (2*SECW)
#define NSTG 5
#define SMEM_BYTES (NSTG*STW*4)   // 61440

__global__ __launch_bounds__(256, 2)
void hgemm_kernel(int M, int K, int nq, int nk,
                  const __half* __restrict__ Ah,
                  const __half* __restrict__ qBh, float* __restrict__ qC, int qN,
                  const __half* __restrict__ kBh, float* __restrict__ kC,
                  const __half* __restrict__ vBh, float* __restrict__ vC) {
    extern __shared__ uint32_t smem[];
    const uint32_t smem_u32 = (uint32_t)__cvta_generic_to_shared(smem);

    const int cx = blockIdx.x;
    const __half* Bh;
    float* C;
    int N, ccol;
    if (cx < nq)           { Bh = qBh; C = qC; N = qN;  ccol = cx; }
    else if (cx < nq + nk) { Bh = kBh; C = kC; N = 256; ccol = cx - nq; }
    else                   { Bh = vBh; C = vC; N = 256; ccol = cx - nq - nk; }

    const int tid = threadIdx.x, lane = tid & 31, warp = tid >> 5;
    const int warpM = warp & 1, warpN = warp >> 1;
    const int cRow = blockIdx.y;

    const int row = tid >> 1, half = tid & 1;
    const __half* aH = Ah + (size_t)(cRow*128 + row)*K + half*8;
    const __half* bH = Bh + (size_t)(ccol*128 + row)*K + half*8;
    const uint32_t dstw = row*LDWW + half*4;

    const int l7 = lane & 7;
    const uint32_t aoffw = (uint32_t)((warpM*64 + l7 + ((lane>>3)&1)*8)*LDWW + (lane>>4)*4);
    uint32_t boffw[2];
    #pragma unroll
    for (int p = 0; p < 2; p++)
        boffw[p] = (uint32_t)((warpN*32 + p*16 + l7 + ((lane>>4)&1)*8)*LDWW + ((lane>>3)&1)*4);

    float acc[4][4][4];
    #pragma unroll
    for (int mt = 0; mt < 4; mt++)
        #pragma unroll
        for (int nt = 0; nt < 4; nt++)
            #pragma unroll
            for (int i = 0; i < 4; i++) acc[mt][nt][i] = 0.f;

    const int KT = K >> 4;

    #pragma unroll
    for (int s = 0; s < NSTG - 1; s++) {
        const int ko = s*16;
        const uint32_t sb = smem_u32 + (s*STW)*4;
        cp16s(sb + dstw*4,          aH + ko);
        cp16s(sb + (SECW + dstw)*4, bH + ko);
        cp_commit();
    }

    int sc = 0;
    for (int kt = 0; kt < KT; kt++) {
        if (kt < KT - 3)      { asm volatile("cp.async.wait_group 3;\n"); }
        else if (kt < KT - 2) { asm volatile("cp.async.wait_group 2;\n"); }
        else if (kt < KT - 1) { asm volatile("cp.async.wait_group 1;\n"); }
        else                  { asm volatile("cp.async.wait_group 0;\n"); }
        __syncthreads();

        if (kt + NSTG - 1 < KT) {
            int sl = sc + (NSTG - 1); if (sl >= NSTG) sl -= NSTG;
            const int ko = (kt + NSTG - 1)*16;
            const uint32_t sb = smem_u32 + (sl*STW)*4;
            cp16s(sb + dstw*4,          aH + ko);
            cp16s(sb + (SECW + dstw)*4, bH + ko);
            cp_commit();
        }

        const uint32_t sb = smem_u32 + (sc*STW)*4;

        uint32_t bhf[2][4];
        #pragma unroll
        for (int p = 0; p < 2; p++)
            ldsm4(bhf[p], sb + (SECW + boffw[p])*4);

        #pragma unroll
        for (int mt = 0; mt < 4; mt++) {
            uint32_t ahf[4];
            ldsm4(ahf, sb + (aoffw + mt*16*LDWW)*4);
            #pragma unroll
            for (int nt = 0; nt < 4; nt++) {
                const uint32_t* bp = &bhf[nt >> 1][(nt & 1)*2];
                mma_f16(acc[mt][nt], ahf, bp);
            }
        }
        sc = (sc + 1 == NSTG) ? 0 : sc + 1;
    }

    const int g = lane >> 2, t4 = lane & 3;
    float* Cb = C + (size_t)cRow*128*N + ccol*128;
    #pragma unroll
    for (int mt = 0; mt < 4; mt++) {
        const int r0 = warpM*64 + mt*16 + g;
        #pragma unroll
        for (int nt = 0; nt < 4; nt++) {
            const int c = warpN*32 + nt*8 + t4*2;
            *(float2*)&Cb[(size_t)r0 * N + c]       = make_float2(acc[mt][nt][0], acc[mt][nt][1]);
            *(float2*)&Cb[(size_t)(r0 + 8) * N + c] = make_float2(acc[mt][nt][2], acc[mt][nt][3]);
        }
    }
}

// ============================================================================
// hedgehog2 (measured config) — now writes fp16 output (half2 stores)
// ============================================================================
#define XS_STRIDE 260
#define FS_STRIDE 68
#define HG_SMEM ((64*XS_STRIDE + 64*FS_STRIDE + 128)*4)

__global__ __launch_bounds__(256, 2)
void hedgehog2_kernel(const float* __restrict__ x,
                      const float* __restrict__ cs,
                      const float* __restrict__ sn,
                      const float* __restrict__ fm,
                      __half* __restrict__ outf,
                      int xh, float scale) {
    extern __shared__ float sm[];
    float* xs = sm;
    float* fs = sm + 64*XS_STRIDE;
    float* mz = fs + 64*FS_STRIDE;

    const int h = blockIdx.y, b = blockIdx.z;
    const int l0 = blockIdx.x * 64;
    const int t = threadIdx.x;
    const int srcH = (xh == 1) ? 0 : h;

    const float* xb = x + ((size_t)(b*L_ + l0)*xh + srcH)*HD_;
    const size_t xstride = (size_t)xh*HD_;
    #pragma unroll
    for (int p = 0; p < 16; p++) {
        int idx4 = p*256 + t;
        int r = idx4 >> 6, c4 = idx4 & 63;
        float4 v = *(const float4*)&xb[r*xstride + c4*4];
        *(float4*)&xs[r*XS_STRIDE + c4*4] = v;
    }
    __syncthreads();

    #pragma unroll
    for (int p = 0; p < 32; p++) {
        int e = p*256 + t;
        int r = e >> 7, j = e & 127;
        float c = cs[(l0 + r)*HALF_ + j];
        float s = sn[(l0 + r)*HALF_ + j];
        float x1 = xs[r*XS_STRIDE + j], x2 = xs[r*XS_STRIDE + j + 128];
        xs[r*XS_STRIDE + j]       = x1*c - x2*s;
        xs[r*XS_STRIDE + j + 128] = x1*s + x2*c;
    }
    __syncthreads();

    const int tr = t >> 4, tc = t & 15;
    float acc[4][4];
    #pragma unroll
    for (int i = 0; i < 4; i++)
        #pragma unroll
        for (int j = 0; j < 4; j++) acc[i][j] = 0.f;

    const float* fmh = fm + (size_t)h*HD_*FD_;
    for (int dt = 0; dt < 4; dt++) {
        #pragma unroll
        for (int p = 0; p < 4; p++) {
            int idx4 = p*256 + t;
            int r = idx4 >> 4, c4 = idx4 & 15;
            float4 v = *(const float4*)&fmh[(size_t)(dt*64 + r)*FD_ + c4*4];
            *(float4*)&fs[r*FS_STRIDE + c4*4] = v;
        }
        __syncthreads();

        #pragma unroll 4
        for (int dd = 0; dd < 64; dd += 4) {
            float4 xv[4], fv[4];
            #pragma unroll
            for (int i = 0; i < 4; i++)
                xv[i] = *(const float4*)&xs[(tr*4 + i)*XS_STRIDE + dt*64 + dd];
            #pragma unroll
            for (int k = 0; k < 4; k++)
                fv[k] = *(const float4*)&fs[(dd + k)*FS_STRIDE + tc*4];
            #pragma unroll
            for (int i = 0; i < 4; i++) {
                float* fvp0 = (float*)&fv[0];
                float* fvp1 = (float*)&fv[1];
                float* fvp2 = (float*)&fv[2];
                float* fvp3 = (float*)&fv[3];
                #pragma unroll
                for (int j = 0; j < 4; j++)
                    acc[i][j] += xv[i].x*fvp0[j] + xv[i].y*fvp1[j]
                               + xv[i].z*fvp2[j] + xv[i].w*fvp3[j];
            }
        }
        __syncthreads();
    }

    #pragma unroll
    for (int i = 0; i < 4; i++)
        *(float4*)&fs[(tr*4 + i)*FS_STRIDE + tc*4] =
            make_float4(acc[i][0], acc[i][1], acc[i][2], acc[i][3]);
    __syncthreads();

    const int warp = t >> 5, lane = t & 31;
    for (int rr = 0; rr < 8; rr++) {
        int rowi = warp*8 + rr;
        float v0 = fs[rowi*FS_STRIDE + lane];
        float v1 = fs[rowi*FS_STRIDE + lane + 32];
        float m = fmaxf(fabsf(v0), fabsf(v1));
        #pragma unroll
        for (int off = 16; off > 0; off >>= 1)
            m = fmaxf(m, __shfl_xor_sync(0xFFFFFFFF, m, off));
        float z = __expf(v0 - m) + __expf(-v0 - m)
                + __expf(v1 - m) + __expf(-v1 - m);
        #pragma unroll
        for (int off = 16; off > 0; off >>= 1)
            z += __shfl_xor_sync(0xFFFFFFFF, z, off);
        if (lane == 0) { mz[rowi] = m; mz[64 + rowi] = z; }
    }
    __syncthreads();

    __half* ob = outf + ((size_t)(b*H_ + h)*L_ + l0)*FEAT_;
    #pragma unroll
    for (int p = 0; p < 8; p++) {
        int idx4 = p*256 + t;
        int rowi = idx4 >> 5, c4 = idx4 & 31;
        int f = c4*4;
        float m = mz[rowi], z = mz[64 + rowi];
        float inv = scale / z;
        float4 pv;
        if (f < 64) {
            pv = *(const float4*)&fs[rowi*FS_STRIDE + f];
            pv.x = __expf(pv.x - m)*inv; pv.y = __expf(pv.y - m)*inv;
            pv.z = __expf(pv.z - m)*inv; pv.w = __expf(pv.w - m)*inv;
        } else {
            pv = *(const float4*)&fs[rowi*FS_STRIDE + f - 64];
            pv.x = __expf(-pv.x - m)*inv; pv.y = __expf(-pv.y - m)*inv;
            pv.z = __expf(-pv.z - m)*inv; pv.w = __expf(-pv.w - m)*inv;
        }
        __half2 h0 = __floats2half2_rn(pv.x, pv.y);
        __half2 h1 = __floats2half2_rn(pv.z, pv.w);
        *(__half2*)&ob[(size_t)rowi*FEAT_ + f]     = h0;
        *(__half2*)&ob[(size_t)rowi*FEAT_ + f + 2] = h1;
    }
}

// ---------------- per-chunk kv state (kf now fp16 input) -------------------
__global__ __launch_bounds__(256)
void kv2_kernel(const __half* __restrict__ kf, const float* __restrict__ v,
                float* __restrict__ kv) {
    __shared__ float ks[32][FEAT_];
    __shared__ float vs[32][128];
    int n  = blockIdx.x;
    int dh = blockIdx.y;
    int bh = blockIdx.z;
    int b  = bh / H_;
    int t  = threadIdx.x;
    int tf = t >> 4;
    int td = t & 15;

    const __half* kfp = kf + ((size_t)bh*L_ + n*CHUNK_)*FEAT_;
    const float*  vp  = v  + ((size_t)b*L_  + n*CHUNK_)*HD_ + dh*128;

    float acc[8][8];
    #pragma unroll
    for (int i = 0; i < 8; i++)
        #pragma unroll
        for (int j = 0; j < 8; j++) acc[i][j] = 0.f;

    float* ksf = &ks[0][0];
    for (int cc = 0; cc < 2; cc++) {
        for (int e = t; e < 32*FEAT_/2; e += 256) {
            __half2 hv = *(const __half2*)&kfp[cc*32*FEAT_ + e*2];
            float2 f2 = __half22float2(hv);
            ksf[e*2] = f2.x; ksf[e*2 + 1] = f2.y;
        }
        for (int e = t; e < 32*128; e += 256) {
            int r = e >> 7, c = e & 127;
            vs[r][c] = vp[(size_t)(cc*32 + r)*HD_ + c];
        }
        __syncthreads();

        #pragma unroll 4
        for (int c = 0; c < 32; c++) {
            float4 ka = *(const float4*)&ks[c][tf*8];
            float4 kb = *(const float4*)&ks[c][tf*8 + 4];
            float4 va = *(const float4*)&vs[c][td*4];
            float4 vb = *(const float4*)&vs[c][64 + td*4];
            float kk[8] = {ka.x,ka.y,ka.z,ka.w,kb.x,kb.y,kb.z,kb.w};
            float vv[8] = {va.x,va.y,va.z,va.w,vb.x,vb.y,vb.z,vb.w};
            #pragma unroll
            for (int i = 0; i < 8; i++)
                #pragma unroll
                for (int j = 0; j < 8; j++)
                    acc[i][j] += kk[i]*vv[j];
        }
        __syncthreads();
    }

    float* out = kv + ((size_t)(bh*NCH_ + n)*FEAT_)*HD_ + dh*128;
    #pragma unroll
    for (int i = 0; i < 8; i++) {
        size_t ro = (size_t)(tf*8 + i)*HD_;
        *(float4*)&out[ro + td*4]      = make_float4(acc[i][0], acc[i][1], acc[i][2], acc[i][3]);
        *(float4*)&out[ro + 64 + td*4] = make_float4(acc[i][4], acc[i][5], acc[i][6], acc[i][7]);
    }
}

// ---------------- exclusive cumsum: fp32 accumulate -> fp16 prefix out -----
__global__ void cumsum_kernel(const float* __restrict__ kv,
                              __half* __restrict__ kvh) {
    int bh = blockIdx.y;
    int e2 = (blockIdx.x*256 + threadIdx.x)*2;
    const float* base = kv  + (size_t)bh*NCH_*FEAT_*HD_ + e2;
    __half*      ob   = kvh + (size_t)bh*NCH_*FEAT_*HD_ + e2;
    float r0 = 0.f, r1 = 0.f;
    for (int n = 0; n < NCH_; n++) {
        float2 t = *(const float2*)&base[(size_t)n*FEAT_*HD_];
        *(__half2*)&ob[(size_t)n*FEAT_*HD_] = __floats2half2_rn(r0, r1);
        r0 += t.x; r1 += t.y;
    }
}

// ============================================================================
// attn3: tensor-core chunk attention.
// Per block (n, h, b): out[64,256] = qf(64x128) @ kvh(128x256)
//                                  + tril(qf @ kf^T)(64x64) @ v(64x256).
// qf/kf loaded to smem; kvh/v streamed as 16x256 fp16 chunks (double buffer).
// Phase B uses non-trans ldmatrix (kf stored [n][k]); streamed B uses
// ldmatrix.trans (row-major [k][n]).
// ============================================================================
#define AQ_STRIDE  136
#define ASS_STRIDE 72
#define ACH_STRIDE 264
#define OFF_QS 0
#define OFF_KS (64*AQ_STRIDE)            // 8704 halves
#define OFF_SS (2*64*AQ_STRIDE)          // 17408
#define OFF_CH (OFF_SS + 64*ASS_STRIDE)  // 22016
#define ATT_SMEM ((OFF_CH + 2*16*ACH_STRIDE)*2)  // 60928 bytes

__global__ __launch_bounds__(256, 2)
void attn3_kernel(const __half* __restrict__ qfh, const __half* __restrict__ kfh,
                  const __half* __restrict__ vh,  const __half* __restrict__ kvh,
                  __half* __restrict__ oh) {
    extern __shared__ __half shm[];
    const uint32_t sb = (uint32_t)__cvta_generic_to_shared(shm);
    const int n = blockIdx.x, h = blockIdx.y, b = blockIdx.z;
    const int bh = b*H_ + h;
    const int tid = threadIdx.x, lane = tid & 31, warp = tid >> 5;
    const int l7 = lane & 7;

    // load qf and kf tiles (64 x 128 halves each)
    const __half* qp = qfh + ((size_t)bh*L_ + n*64)*FEAT_;
    const __half* kp = kfh + ((size_t)bh*L_ + n*64)*FEAT_;
    #pragma unroll
    for (int i = 0; i < 4; i++) {
        int idx = i*256 + tid;
        int r = idx >> 4, c8 = (idx & 15)*8;
        cp16s(sb + (OFF_QS + r*AQ_STRIDE + c8)*2, qp + r*FEAT_ + c8);
        cp16s(sb + (OFF_KS + r*AQ_STRIDE + c8)*2, kp + r*FEAT_ + c8);
    }
    cp_commit();
    asm volatile("cp.async.wait_group 0;\n");
    __syncthreads();

    // -------- phase B: s = tril(qf @ kf^T), store fp16 to ss --------
    {
        const int m0 = (warp & 3)*16;
        const int n0 = (warp >> 2)*32;
        float sacc[4][4];
        #pragma unroll
        for (int nt = 0; nt < 4; nt++)
            #pragma unroll
            for (int i = 0; i < 4; i++) sacc[nt][i] = 0.f;

        const uint32_t arow = m0 + l7 + ((lane>>3)&1)*8;
        const uint32_t acol = (lane>>4)*8;
        uint32_t brow[2];
        #pragma unroll
        for (int p = 0; p < 2; p++)
            brow[p] = n0 + p*16 + l7 + ((lane>>4)&1)*8;
        const uint32_t bcol = ((lane>>3)&1)*8;

        #pragma unroll
        for (int kk = 0; kk < 8; kk++) {
            uint32_t af[4];
            ldsm4(af, sb + (OFF_QS + arow*AQ_STRIDE + acol + kk*16)*2);
            uint32_t bf[2][4];
            #pragma unroll
            for (int p = 0; p < 2; p++)
                ldsm4(bf[p], sb + (OFF_KS + brow[p]*AQ_STRIDE + bcol + kk*16)*2);
            #pragma unroll
            for (int nt = 0; nt < 4; nt++)
                mma_f16(sacc[nt], af, &bf[nt>>1][(nt&1)*2]);
        }

        const int g = lane >> 2, t4 = lane & 3;
        #pragma unroll
        for (int nt = 0; nt < 4; nt++) {
            int col = n0 + nt*8 + t4*2;
            int r0 = m0 + g, r1 = r0 + 8;
            float v00 = (col   <= r0) ? sacc[nt][0] : 0.f;
            float v01 = (col+1 <= r0) ? sacc[nt][1] : 0.f;
            float v10 = (col   <= r1) ? sacc[nt][2] : 0.f;
            float v11 = (col+1 <= r1) ? sacc[nt][3] : 0.f;
            *(__half2*)&shm[OFF_SS + r0*ASS_STRIDE + col] = __floats2half2_rn(v00, v01);
            *(__half2*)&shm[OFF_SS + r1*ASS_STRIDE + col] = __floats2half2_rn(v10, v11);
        }
    }
    __syncthreads();

    // -------- phases A + C: out = qf@kvh + ss@v --------
    const int m0 = (warp & 3)*16;
    const int n0 = (warp >> 2)*128;
    float acc[16][4];
    #pragma unroll
    for (int nt = 0; nt < 16; nt++)
        #pragma unroll
        for (int i = 0; i < 4; i++) acc[nt][i] = 0.f;

    const __half* kvp = kvh + ((size_t)(bh*NCH_ + n)*FEAT_)*HD_;
    const __half* vp  = vh  + ((size_t)(b*L_ + n*64))*HD_;

    // prologue chunk 0
    {
        const __half* src = kvp;
        const uint32_t cb = sb + OFF_CH*2;
        #pragma unroll
        for (int j = 0; j < 2; j++) {
            int idx = j*256 + tid;
            int r = idx >> 5, c8 = (idx & 31)*8;
            cp16s(cb + (r*ACH_STRIDE + c8)*2, src + (size_t)r*HD_ + c8);
        }
        cp_commit();
    }

    for (int c = 0; c < 12; c++) {
        if (c + 1 < 12) {
            const int i = c + 1;
            const __half* src = (i < 8) ? (kvp + (size_t)(i*16)*HD_)
                                        : (vp  + (size_t)((i-8)*16)*HD_);
            const uint32_t cb = sb + (OFF_CH + (i&1)*16*ACH_STRIDE)*2;
            #pragma unroll
            for (int j = 0; j < 2; j++) {
                int idx = j*256 + tid;
                int r = idx >> 5, c8 = (idx & 31)*8;
                cp16s(cb + (r*ACH_STRIDE + c8)*2, src + (size_t)r*HD_ + c8);
            }
            cp_commit();
            asm volatile("cp.async.wait_group 1;\n");
        } else {
            asm volatile("cp.async.wait_group 0;\n");
        }
        __syncthreads();

        const uint32_t cb = sb + (OFF_CH + (c&1)*16*ACH_STRIDE)*2;

        // A fragment: qf for c<8, ss for c>=8
        uint32_t af[4];
        {
            const uint32_t arow = m0 + l7 + ((lane>>3)&1)*8;
            if (c < 8)
                ldsm4(af, sb + (OFF_QS + arow*AQ_STRIDE + (lane>>4)*8 + c*16)*2);
            else
                ldsm4(af, sb + (OFF_SS + arow*ASS_STRIDE + (lane>>4)*8 + (c-8)*16)*2);
        }

        const uint32_t brow = l7 + ((lane>>3)&1)*8;
        #pragma unroll
        for (int nt16 = 0; nt16 < 8; nt16++) {
            uint32_t bf[4];
            ldsm4t(bf, cb + (brow*ACH_STRIDE + n0 + nt16*16 + (lane>>4)*8)*2);
            mma_f16(acc[nt16*2],     af, &bf[0]);
            mma_f16(acc[nt16*2 + 1], af, &bf[2]);
        }
        __syncthreads();
    }

    // epilogue: fp16 half2 stores
    const int g = lane >> 2, t4 = lane & 3;
    __half* ob = oh + ((size_t)(b*L_ + n*64))*(H_*HD_) + h*HD_;
    #pragma unroll
    for (int nt = 0; nt < 16; nt++) {
        int col = n0 + nt*8 + t4*2;
        int r0 = m0 + g, r1 = r0 + 8;
        *(__half2*)&ob[(size_t)r0*(H_*HD_) + col] = __floats2half2_rn(acc[nt][0], acc[nt][1]);
        *(__half2*)&ob[(size_t)r1*(H_*HD_) + col] = __floats2half2_rn(acc[nt][2], acc[nt][3]);
    }
}

// ---------------- launch ---------------------------------------------------
extern "C" void kernel_launch(void* const* d_in, const int* in_sizes, int n_in,
                              void* d_out, int out_size) {
    const float* hidden = (const float*)d_in[0];
    const float* fcos   = (const float*)d_in[1];
    const float* fsin   = (const float*)d_in[2];
    // d_in[3] = mask (unused)
    const float* Wq     = (const float*)d_in[4];
    const float* Wk     = (const float*)d_in[5];
    const float* Wv     = (const float*)d_in[6];
    const float* Wo     = (const float*)d_in[7];
    const float* fmq    = (const float*)d_in[8];
    const float* fmk    = (const float*)d_in[9];
    float* out          = (float*)d_out;

    float *q, *k, *v, *kv;
    cudaGetSymbolAddress((void**)&q,  g_q);
    cudaGetSymbolAddress((void**)&k,  g_k);
    cudaGetSymbolAddress((void**)&v,  g_v);
    cudaGetSymbolAddress((void**)&kv, g_kv);

    __half *kvh,*qfh,*kfh,*vh,*hh,*oh,*wqh,*wkh,*wvh,*woh;
    cudaGetSymbolAddress((void**)&kvh, g_kvh);
    cudaGetSymbolAddress((void**)&qfh, g_qfh);
    cudaGetSymbolAddress((void**)&kfh, g_kfh);
    cudaGetSymbolAddress((void**)&vh,  g_vh);
    cudaGetSymbolAddress((void**)&hh,  g_hh);
    cudaGetSymbolAddress((void**)&oh,  g_oh);
    cudaGetSymbolAddress((void**)&wqh, g_wqh);
    cudaGetSymbolAddress((void**)&wkh, g_wkh);
    cudaGetSymbolAddress((void**)&wvh, g_wvh);
    cudaGetSymbolAddress((void**)&woh, g_woh);

    cudaFuncSetAttribute(hgemm_kernel,
                         cudaFuncAttributeMaxDynamicSharedMemorySize, SMEM_BYTES);
    cudaFuncSetAttribute(hedgehog2_kernel,
                         cudaFuncAttributeMaxDynamicSharedMemorySize, HG_SMEM);
    cudaFuncSetAttribute(attn3_kernel,
                         cudaFuncAttributeMaxDynamicSharedMemorySize, ATT_SMEM);

    const int M = B_*L_;   // 4096
    const float qscale = 0.08838834764831845f;   // 128^-0.5
    const int halfN = (M*D_)/2;

    // 0: all weight transposes
    splitT_all_kernel<<<dim3(64, 64, 4), 256>>>(Wq, wqh, Wo, woh, Wk, wkh, Wv, wvh);
    // 1,2: convert hidden -> fp16 (two halves)
    cvt_kernel<<<halfN/2048, 256>>>(hidden, hh, 0,     halfN);
    cvt_kernel<<<halfN/2048, 256>>>(hidden, hh, halfN, halfN);
    // 3: fused Q+K+V projections (PROFILED slot)
    hgemm_kernel<<<dim3(20, M/128), 256, SMEM_BYTES>>>(M, D_, 16, 2,
        hh, wqh, q, H_*HD_, wkh, k, wvh, v);
    // 4: hedgehog q (fused RoPE) -> fp16
    hedgehog2_kernel<<<dim3(L_/64, H_, B_), 256, HG_SMEM>>>(q, fcos, fsin, fmq, qfh, H_, qscale);
    // 5: hedgehog k -> fp16
    hedgehog2_kernel<<<dim3(L_/64, H_, B_), 256, HG_SMEM>>>(k, fcos, fsin, fmk, kfh, 1, 1.0f);
    // 6: convert v -> fp16
    cvt_kernel<<<(B_*L_*HD_)/2048, 256>>>(v, vh, 0, B_*L_*HD_);
    // 7: per-chunk kv states
    kv2_kernel<<<dim3(NCH_, 2, B_*H_), 256>>>(kfh, v, kv);
    // 8: exclusive cumsum (fp32 accumulate -> fp16 prefix)
    cumsum_kernel<<<dim3(64, B_*H_), 256>>>(kv, kvh);
    // 9: tensor-core attention -> fp16 oh
    attn3_kernel<<<dim3(NCH_, H_, B_), 256, ATT_SMEM>>>(qfh, kfh, vh, kvh, oh);
    // 10: output projection
    hgemm_kernel<<<dim3(16, M/128), 256, SMEM_BYTES>>>(M, H_*HD_, 16, 0,
        oh, woh, out, D_, woh, out, woh, out);
}